// round 1
// baseline (speedup 1.0000x reference)
#include <cuda_runtime.h>

// Problem constants
#define BATCH 8192
#define NAG   64      // agents per batch
#define DIN   128
#define EMB   32

// Shared-memory layout (in floats)
#define SM_W1   0        // 128*32 = 4096
#define SM_C    4096     // 32*32  = 1024
#define SM_W2   5120     // 64
#define SM_B1   5184     // 32
#define SM_B2   5216     // 16 (pad)
#define SM_FI   5232     // 64*36 = 2304  (fi, row stride 36)
#define SM_FIT  7536     // 32*68 = 2176  (fi^T, row stride 68)
#define SM_A    9712     // union region, 64*132 = 8448 floats
                         //   phase1: sIn  (64 x stride 132)
                         //   later : sG (64*36=2304) + sBeta at +2304 (64*65=4160)
#define SM_TOTAL (9712 + 8448)   // 18160 floats = 72640 bytes

// ---- packed f32x2 helpers (PTX ISA 8.6, sm_100+) ----
__device__ __forceinline__ unsigned long long splat2(float x) {
    unsigned long long r;
    asm("mov.b64 %0, {%1, %1};" : "=l"(r) : "f"(x));
    return r;
}
__device__ __forceinline__ unsigned long long pack2(float x, float y) {
    unsigned long long r;
    asm("mov.b64 %0, {%1, %2};" : "=l"(r) : "f"(x), "f"(y));
    return r;
}
__device__ __forceinline__ void fma2(unsigned long long& d,
                                     unsigned long long a,
                                     unsigned long long b) {
    asm("fma.rn.f32x2 %0, %1, %2, %0;" : "+l"(d) : "l"(a), "l"(b));
}
__device__ __forceinline__ float2 unpack2(unsigned long long v) {
    float2 f;
    asm("mov.b64 {%0, %1}, %2;" : "=f"(f.x), "=f"(f.y) : "l"(v));
    return f;
}

__global__ void __launch_bounds__(256, 3)
attn_fused_kernel(const float* __restrict__ inp,
                  const float* __restrict__ gW1,
                  const float* __restrict__ gb1,
                  const float* __restrict__ gC,
                  const float* __restrict__ gW2,
                  const float* __restrict__ gb2,
                  float* __restrict__ out)
{
    extern __shared__ float sm[];
    const int tid = threadIdx.x;
    const int b   = blockIdx.x;
    const int r   = tid >> 2;   // 0..63  (agent row)
    const int c   = tid & 3;    // 0..3   (column group)
    const int col0 = c << 3;    // first of 8 output cols (E dim)

    float* sW1  = sm + SM_W1;
    float* sC   = sm + SM_C;
    float* sW2  = sm + SM_W2;
    float* sB1  = sm + SM_B1;
    float* sB2  = sm + SM_B2;
    float* sFi  = sm + SM_FI;
    float* sFiT = sm + SM_FIT;
    float* sIn  = sm + SM_A;            // stride 132
    float* sG   = sm + SM_A;            // stride 36 (reuses sIn space)
    float* sBeta = sm + SM_A + 2304;    // stride 65

    // ---------------- Phase 0: stage weights + input tile ----------------
    {
        const float4* w4 = (const float4*)gW1;
        float4* s4 = (float4*)sW1;
        #pragma unroll
        for (int i = 0; i < 4; ++i) s4[tid + i * 256] = w4[tid + i * 256];

        ((float4*)sC)[tid] = ((const float4*)gC)[tid];   // 1024 floats = 256 f4
        if (tid < 64) sW2[tid] = gW2[tid];
        if (tid < 32) sB1[tid] = gb1[tid];
        if (tid == 0) sB2[0] = gb2[0];

        const float4* in4 = (const float4*)(inp + (size_t)b * (NAG * DIN));
        #pragma unroll
        for (int i = 0; i < 8; ++i) {
            int idx = tid + i * 256;          // 0..2047
            int row = idx >> 5;               // /32  (32 float4 per row)
            int cc  = idx & 31;
            *(float4*)(sIn + row * 132 + (cc << 2)) = in4[idx];
        }
    }
    __syncthreads();

    // ---------------- Phase 1: fc1  fi = relu(inp @ W1 + b1) --------------
    {
        unsigned long long a0 = 0, a1 = 0, a2 = 0, a3 = 0;
        const float*  aRow = sIn + r * 132;
        const float4* wB   = (const float4*)sW1 + (c << 1);
        #pragma unroll 4
        for (int k = 0; k < DIN; ++k) {
            unsigned long long av2 = splat2(aRow[k]);
            float4 w0 = wB[k * 8];
            float4 w1 = wB[k * 8 + 1];
            fma2(a0, av2, pack2(w0.x, w0.y));
            fma2(a1, av2, pack2(w0.z, w0.w));
            fma2(a2, av2, pack2(w1.x, w1.y));
            fma2(a3, av2, pack2(w1.z, w1.w));
        }
        float2 f0 = unpack2(a0), f1 = unpack2(a1), f2 = unpack2(a2), f3 = unpack2(a3);
        float v[8] = {f0.x, f0.y, f1.x, f1.y, f2.x, f2.y, f3.x, f3.y};
        #pragma unroll
        for (int t = 0; t < 8; ++t) {
            float x = v[t] + sB1[col0 + t];
            x = fmaxf(x, 0.0f);
            sFi[r * 36 + col0 + t] = x;
            sFiT[(col0 + t) * 68 + r] = x;
        }
    }
    __syncthreads();   // sIn is now dead; sG may be written

    // ---------------- Phase 2: g = fi @ C ---------------------------------
    {
        unsigned long long a0 = 0, a1 = 0, a2 = 0, a3 = 0;
        const float*  fRow = sFi + r * 36;
        const float4* cB   = (const float4*)sC + (c << 1);
        #pragma unroll 8
        for (int e = 0; e < EMB; ++e) {
            unsigned long long av2 = splat2(fRow[e]);
            float4 w0 = cB[e * 8];
            float4 w1 = cB[e * 8 + 1];
            fma2(a0, av2, pack2(w0.x, w0.y));
            fma2(a1, av2, pack2(w0.z, w0.w));
            fma2(a2, av2, pack2(w1.x, w1.y));
            fma2(a3, av2, pack2(w1.z, w1.w));
        }
        float2 f0 = unpack2(a0), f1 = unpack2(a1), f2 = unpack2(a2), f3 = unpack2(a3);
        sG[r * 36 + col0 + 0] = f0.x;  sG[r * 36 + col0 + 1] = f0.y;
        sG[r * 36 + col0 + 2] = f1.x;  sG[r * 36 + col0 + 3] = f1.y;
        sG[r * 36 + col0 + 4] = f2.x;  sG[r * 36 + col0 + 5] = f2.y;
        sG[r * 36 + col0 + 6] = f3.x;  sG[r * 36 + col0 + 7] = f3.y;
    }
    __syncthreads();

    // -------- Phase 3: beta = g @ fi^T, diag mask, row softmax ------------
    {
        unsigned long long bb0 = 0, bb1 = 0, bb2 = 0, bb3 = 0;
        unsigned long long bb4 = 0, bb5 = 0, bb6 = 0, bb7 = 0;
        const float* gRow = sG + r * 36;
        const int j0 = c << 4;                    // 16 j-columns per thread
        #pragma unroll 4
        for (int e = 0; e < EMB; ++e) {
            unsigned long long av2 = splat2(gRow[e]);
            const float4* p = (const float4*)(sFiT + e * 68 + j0);
            float4 q0 = p[0], q1 = p[1], q2 = p[2], q3 = p[3];
            fma2(bb0, av2, pack2(q0.x, q0.y));
            fma2(bb1, av2, pack2(q0.z, q0.w));
            fma2(bb2, av2, pack2(q1.x, q1.y));
            fma2(bb3, av2, pack2(q1.z, q1.w));
            fma2(bb4, av2, pack2(q2.x, q2.y));
            fma2(bb5, av2, pack2(q2.z, q2.w));
            fma2(bb6, av2, pack2(q3.x, q3.y));
            fma2(bb7, av2, pack2(q3.z, q3.w));
        }
        float v16[16];
        {
            float2 u;
            u = unpack2(bb0); v16[0]  = u.x; v16[1]  = u.y;
            u = unpack2(bb1); v16[2]  = u.x; v16[3]  = u.y;
            u = unpack2(bb2); v16[4]  = u.x; v16[5]  = u.y;
            u = unpack2(bb3); v16[6]  = u.x; v16[7]  = u.y;
            u = unpack2(bb4); v16[8]  = u.x; v16[9]  = u.y;
            u = unpack2(bb5); v16[10] = u.x; v16[11] = u.y;
            u = unpack2(bb6); v16[12] = u.x; v16[13] = u.y;
            u = unpack2(bb7); v16[14] = u.x; v16[15] = u.y;
        }
        // mask diagonal (self-attention excluded)
        {
            int d = r - j0;
            if (d >= 0 && d < 16) v16[d] = -1e30f;
        }
        // row max across this thread's 16 + 3 partner threads (same r)
        float m = v16[0];
        #pragma unroll
        for (int t = 1; t < 16; ++t) m = fmaxf(m, v16[t]);
        m = fmaxf(m, __shfl_xor_sync(0xffffffffu, m, 1));
        m = fmaxf(m, __shfl_xor_sync(0xffffffffu, m, 2));
        float s = 0.0f;
        #pragma unroll
        for (int t = 0; t < 16; ++t) {
            float e = __expf(v16[t] - m);
            v16[t] = e;
            s += e;
        }
        s += __shfl_xor_sync(0xffffffffu, s, 1);
        s += __shfl_xor_sync(0xffffffffu, s, 2);
        float inv = __frcp_rn(s);
        #pragma unroll
        for (int t = 0; t < 16; ++t) sBeta[r * 65 + j0 + t] = v16[t] * inv;
    }
    __syncthreads();

    // ---- Phase 4: v = alpha @ fi, fused fc2 dot + sigmoid epilogue -------
    {
        unsigned long long a0 = 0, a1 = 0, a2 = 0, a3 = 0;
        const float* aRow = sBeta + r * 65;
        #pragma unroll 4
        for (int j = 0; j < NAG; ++j) {
            unsigned long long av2 = splat2(aRow[j]);
            const float4* p = (const float4*)(sFi + j * 36 + col0);
            float4 q0 = p[0], q1 = p[1];
            fma2(a0, av2, pack2(q0.x, q0.y));
            fma2(a1, av2, pack2(q0.z, q0.w));
            fma2(a2, av2, pack2(q1.x, q1.y));
            fma2(a3, av2, pack2(q1.z, q1.w));
        }
        float2 f0 = unpack2(a0), f1 = unpack2(a1), f2 = unpack2(a2), f3 = unpack2(a3);
        float vv[8] = {f0.x, f0.y, f1.x, f1.y, f2.x, f2.y, f3.x, f3.y};

        float part = 0.0f;
        #pragma unroll
        for (int t = 0; t < 8; ++t) {
            part += vv[t] * sW2[EMB + col0 + t];            // v half
            part += sFi[r * 36 + col0 + t] * sW2[col0 + t]; // fi half
        }
        part += __shfl_xor_sync(0xffffffffu, part, 1);
        part += __shfl_xor_sync(0xffffffffu, part, 2);
        if (c == 0) {
            float z = part + sB2[0];
            out[(size_t)b * NAG + r] = 1.0f / (1.0f + __expf(-z));
        }
    }
}

extern "C" void kernel_launch(void* const* d_in, const int* in_sizes, int n_in,
                              void* d_out, int out_size)
{
    const float* inp = (const float*)d_in[0];
    const float* W1  = (const float*)d_in[1];
    const float* b1  = (const float*)d_in[2];
    const float* C   = (const float*)d_in[3];
    const float* W2  = (const float*)d_in[4];
    const float* b2  = (const float*)d_in[5];
    float* out = (float*)d_out;

    const int smem_bytes = SM_TOTAL * (int)sizeof(float);
    cudaFuncSetAttribute(attn_fused_kernel,
                         cudaFuncAttributeMaxDynamicSharedMemorySize, smem_bytes);
    attn_fused_kernel<<<BATCH, 256, smem_bytes>>>(inp, W1, b1, C, W2, b2, out);
}

// round 2
// speedup vs baseline: 2.2383x; 2.2383x over previous
#include <cuda_runtime.h>

typedef unsigned long long ull;

#define BATCH 8192
#define NAG   64
#define DIN   128
#define EMB   32

// Shared layout (float offsets)
#define SM_W1     0        // 128*32
#define SM_C      4096     // 32*32
#define SM_W2     5120     // 64
#define SM_B1     5184     // 32
#define SM_B2     5216     // (+pad to 5232)
#define SM_FI     5232     // 64 rows, stride 36
#define SM_FIT    7536     // 32 rows, stride 68
#define SM_A      9712     // union: sIn(64x132) | sPart(2048)->later g(64x36)+alphaT(64x68)
#define SM_G      SM_A
#define SM_ALPHAT (SM_A + 2304)
#define SM_PART   SM_A
#define SM_TOTAL  (9712 + 8448)   // 18160 floats = 72640 B

// ---- packed f32x2 + vector smem helpers ----
__device__ __forceinline__ ull splat2(float x) {
    ull r; asm("mov.b64 %0, {%1, %1};" : "=l"(r) : "f"(x)); return r;
}
__device__ __forceinline__ void fma2(ull& d, ull a, ull b) {
    asm("fma.rn.f32x2 %0, %1, %2, %0;" : "+l"(d) : "l"(a), "l"(b));
}
__device__ __forceinline__ void add2(ull& d, ull a, ull b) {
    asm("add.rn.f32x2 %0, %1, %2;" : "=l"(d) : "l"(a), "l"(b));
}
__device__ __forceinline__ float2 unpack2(ull v) {
    float2 f; asm("mov.b64 {%0, %1}, %2;" : "=f"(f.x), "=f"(f.y) : "l"(v)); return f;
}
__device__ __forceinline__ void lds16(ull& lo, ull& hi, unsigned addr) {
    asm volatile("ld.shared.v2.u64 {%0, %1}, [%2];" : "=l"(lo), "=l"(hi) : "r"(addr));
}
__device__ __forceinline__ void sts16(unsigned addr, ull lo, ull hi) {
    asm volatile("st.shared.v2.u64 [%0], {%1, %2};" :: "r"(addr), "l"(lo), "l"(hi) : "memory");
}

__global__ void __launch_bounds__(256, 3)
attn_fused_kernel(const float* __restrict__ inp,
                  const float* __restrict__ gW1,
                  const float* __restrict__ gb1,
                  const float* __restrict__ gC,
                  const float* __restrict__ gW2,
                  const float* __restrict__ gb2,
                  float* __restrict__ out)
{
    extern __shared__ float sm[];
    const int tid = threadIdx.x;
    const int b   = blockIdx.x;
    const unsigned smemB = (unsigned)__cvta_generic_to_shared(sm);

    // ---------------- Phase 0: stage weights + input tile ----------------
    {
        const float4* w4 = (const float4*)gW1;
        float4* s4 = (float4*)(sm + SM_W1);
        #pragma unroll
        for (int i = 0; i < 4; ++i) s4[tid + i * 256] = w4[tid + i * 256];

        ((float4*)(sm + SM_C))[tid] = ((const float4*)gC)[tid];
        if (tid < 64) sm[SM_W2 + tid] = gW2[tid];
        if (tid < 32) sm[SM_B1 + tid] = gb1[tid];
        if (tid == 0) sm[SM_B2] = gb2[0];

        const float4* in4 = (const float4*)(inp + (size_t)b * (NAG * DIN));
        #pragma unroll
        for (int i = 0; i < 8; ++i) {
            int idx = tid + i * 256;          // 0..2047
            int row = idx >> 5;
            int cc  = idx & 31;
            *(float4*)(sm + SM_A + row * 132 + (cc << 2)) = in4[idx];
        }
    }
    __syncthreads();

    const int h = tid >> 7;       // k-split half
    const int u = tid & 127;

    // -------- Phase 1: fc1  fi = relu(inp @ W1 + b1), k-split-2, 4x4 tile ----
    {
        const int rg = u >> 3, cg = u & 7;
        const int r0 = rg << 2, c0 = cg << 2;
        ull acc[4][2] = {{0,0},{0,0},{0,0},{0,0}};

        const float* aP = sm + SM_A + r0 * 132 + (h << 6);
        const unsigned wA = smemB + (unsigned)(SM_W1 + (h << 6) * 32 + c0) * 4u;

        #pragma unroll 4
        for (int kq = 0; kq < 16; ++kq) {
            float4 A0 = *(const float4*)(aP + 0 * 132 + (kq << 2));
            float4 A1 = *(const float4*)(aP + 1 * 132 + (kq << 2));
            float4 A2 = *(const float4*)(aP + 2 * 132 + (kq << 2));
            float4 A3 = *(const float4*)(aP + 3 * 132 + (kq << 2));
            ull wl[4], wh[4];
            #pragma unroll
            for (int kk = 0; kk < 4; ++kk)
                lds16(wl[kk], wh[kk], wA + (unsigned)((kq << 2) + kk) * 128u);

            float a0[4] = {A0.x, A0.y, A0.z, A0.w};
            float a1[4] = {A1.x, A1.y, A1.z, A1.w};
            float a2[4] = {A2.x, A2.y, A2.z, A2.w};
            float a3[4] = {A3.x, A3.y, A3.z, A3.w};
            #pragma unroll
            for (int kk = 0; kk < 4; ++kk) {
                ull s;
                s = splat2(a0[kk]); fma2(acc[0][0], s, wl[kk]); fma2(acc[0][1], s, wh[kk]);
                s = splat2(a1[kk]); fma2(acc[1][0], s, wl[kk]); fma2(acc[1][1], s, wh[kk]);
                s = splat2(a2[kk]); fma2(acc[2][0], s, wl[kk]); fma2(acc[2][1], s, wh[kk]);
                s = splat2(a3[kk]); fma2(acc[3][0], s, wl[kk]); fma2(acc[3][1], s, wh[kk]);
            }
        }
        __syncthreads();                       // sIn dead; sPart region usable
        const unsigned pA = smemB + (unsigned)(SM_PART + u * 16) * 4u;
        if (h == 1) {
            #pragma unroll
            for (int i = 0; i < 4; ++i) sts16(pA + i * 16u, acc[i][0], acc[i][1]);
        }
        __syncthreads();
        if (h == 0) {
            float4 bb = *(const float4*)(sm + SM_B1 + c0);
            float x[4][4];
            #pragma unroll
            for (int i = 0; i < 4; ++i) {
                ull lo, hi; lds16(lo, hi, pA + i * 16u);
                add2(acc[i][0], acc[i][0], lo);
                add2(acc[i][1], acc[i][1], hi);
                float2 p0 = unpack2(acc[i][0]), p1 = unpack2(acc[i][1]);
                x[i][0] = fmaxf(p0.x + bb.x, 0.0f);
                x[i][1] = fmaxf(p0.y + bb.y, 0.0f);
                x[i][2] = fmaxf(p1.x + bb.z, 0.0f);
                x[i][3] = fmaxf(p1.y + bb.w, 0.0f);
                *(float4*)(sm + SM_FI + (r0 + i) * 36 + c0) =
                    make_float4(x[i][0], x[i][1], x[i][2], x[i][3]);
            }
            #pragma unroll
            for (int j = 0; j < 4; ++j)
                *(float4*)(sm + SM_FIT + (c0 + j) * 68 + r0) =
                    make_float4(x[0][j], x[1][j], x[2][j], x[3][j]);
        }
        __syncthreads();
    }

    // ---------------- Phase 2: g = fi @ C  (2x4 tile) ----------------------
    {
        const int rg = tid >> 3, cg = tid & 7;
        const int r0 = rg << 1, c0 = cg << 2;
        ull acc[2][2] = {{0,0},{0,0}};

        #pragma unroll
        for (int eq = 0; eq < 8; ++eq) {
            const int eb = eq << 2;
            float4 F0 = *(const float4*)(sm + SM_FI + r0 * 36 + eb);
            float4 F1 = *(const float4*)(sm + SM_FI + (r0 + 1) * 36 + eb);
            ull cl[4], ch[4];
            #pragma unroll
            for (int kk = 0; kk < 4; ++kk)
                lds16(cl[kk], ch[kk], smemB + (unsigned)(SM_C + (eb + kk) * 32 + c0) * 4u);
            float f0[4] = {F0.x, F0.y, F0.z, F0.w};
            float f1[4] = {F1.x, F1.y, F1.z, F1.w};
            #pragma unroll
            for (int kk = 0; kk < 4; ++kk) {
                ull s;
                s = splat2(f0[kk]); fma2(acc[0][0], s, cl[kk]); fma2(acc[0][1], s, ch[kk]);
                s = splat2(f1[kk]); fma2(acc[1][0], s, cl[kk]); fma2(acc[1][1], s, ch[kk]);
            }
        }
        #pragma unroll
        for (int i = 0; i < 2; ++i)
            sts16(smemB + (unsigned)(SM_G + (r0 + i) * 36 + c0) * 4u, acc[i][0], acc[i][1]);
        __syncthreads();
    }

    // -------- Phase 3: beta = g @ fi^T, mask, softmax, store alpha^T ------
    {
        const int ig = tid >> 4, jg = tid & 15;
        const int i0 = ig << 2, j0 = jg << 2;
        ull acc[4][2] = {{0,0},{0,0},{0,0},{0,0}};

        #pragma unroll
        for (int eq = 0; eq < 8; ++eq) {
            const int eb = eq << 2;
            float4 G0 = *(const float4*)(sm + SM_G + (i0 + 0) * 36 + eb);
            float4 G1 = *(const float4*)(sm + SM_G + (i0 + 1) * 36 + eb);
            float4 G2 = *(const float4*)(sm + SM_G + (i0 + 2) * 36 + eb);
            float4 G3 = *(const float4*)(sm + SM_G + (i0 + 3) * 36 + eb);
            ull bl[4], bh[4];
            #pragma unroll
            for (int kk = 0; kk < 4; ++kk)
                lds16(bl[kk], bh[kk], smemB + (unsigned)(SM_FIT + (eb + kk) * 68 + j0) * 4u);
            float g0[4] = {G0.x, G0.y, G0.z, G0.w};
            float g1[4] = {G1.x, G1.y, G1.z, G1.w};
            float g2[4] = {G2.x, G2.y, G2.z, G2.w};
            float g3[4] = {G3.x, G3.y, G3.z, G3.w};
            #pragma unroll
            for (int kk = 0; kk < 4; ++kk) {
                ull s;
                s = splat2(g0[kk]); fma2(acc[0][0], s, bl[kk]); fma2(acc[0][1], s, bh[kk]);
                s = splat2(g1[kk]); fma2(acc[1][0], s, bl[kk]); fma2(acc[1][1], s, bh[kk]);
                s = splat2(g2[kk]); fma2(acc[2][0], s, bl[kk]); fma2(acc[2][1], s, bh[kk]);
                s = splat2(g3[kk]); fma2(acc[3][0], s, bl[kk]); fma2(acc[3][1], s, bh[kk]);
            }
        }
        float v[4][4];
        #pragma unroll
        for (int i = 0; i < 4; ++i) {
            float2 p0 = unpack2(acc[i][0]), p1 = unpack2(acc[i][1]);
            v[i][0] = p0.x; v[i][1] = p0.y; v[i][2] = p1.x; v[i][3] = p1.y;
        }
        // diagonal mask
        #pragma unroll
        for (int i = 0; i < 4; ++i) {
            int jd = i0 + i - j0;
            if (jd >= 0 && jd < 4) v[i][jd] = -1e30f;
        }
        // per-row softmax: reduce across 16 jg lanes (xor 1,2,4,8)
        #pragma unroll
        for (int i = 0; i < 4; ++i) {
            float m = fmaxf(fmaxf(v[i][0], v[i][1]), fmaxf(v[i][2], v[i][3]));
            m = fmaxf(m, __shfl_xor_sync(0xffffffffu, m, 1));
            m = fmaxf(m, __shfl_xor_sync(0xffffffffu, m, 2));
            m = fmaxf(m, __shfl_xor_sync(0xffffffffu, m, 4));
            m = fmaxf(m, __shfl_xor_sync(0xffffffffu, m, 8));
            float s = 0.0f;
            #pragma unroll
            for (int j = 0; j < 4; ++j) { v[i][j] = __expf(v[i][j] - m); s += v[i][j]; }
            s += __shfl_xor_sync(0xffffffffu, s, 1);
            s += __shfl_xor_sync(0xffffffffu, s, 2);
            s += __shfl_xor_sync(0xffffffffu, s, 4);
            s += __shfl_xor_sync(0xffffffffu, s, 8);
            float inv = __frcp_rn(s);
            #pragma unroll
            for (int j = 0; j < 4; ++j) v[i][j] *= inv;
        }
        #pragma unroll
        for (int j = 0; j < 4; ++j)
            *(float4*)(sm + SM_ALPHAT + (j0 + j) * 68 + i0) =
                make_float4(v[0][j], v[1][j], v[2][j], v[3][j]);
        __syncthreads();
    }

    // ---- Phase 4: v = alpha @ fi (k-split-2, 4x4) + fc2 + sigmoid --------
    {
        const int ig = u >> 3, eg = u & 7;
        const int i0 = ig << 2, e0 = eg << 2;
        ull acc[4][2] = {{0,0},{0,0},{0,0},{0,0}};

        #pragma unroll 4
        for (int jj = 0; jj < 32; ++jj) {
            const int j = (h << 5) + jj;
            float4 av = *(const float4*)(sm + SM_ALPHAT + j * 68 + i0);
            ull fl, fh;
            lds16(fl, fh, smemB + (unsigned)(SM_FI + j * 36 + e0) * 4u);
            ull s;
            s = splat2(av.x); fma2(acc[0][0], s, fl); fma2(acc[0][1], s, fh);
            s = splat2(av.y); fma2(acc[1][0], s, fl); fma2(acc[1][1], s, fh);
            s = splat2(av.z); fma2(acc[2][0], s, fl); fma2(acc[2][1], s, fh);
            s = splat2(av.w); fma2(acc[3][0], s, fl); fma2(acc[3][1], s, fh);
        }
        __syncthreads();                 // g region dead -> partials
        const unsigned pA = smemB + (unsigned)(SM_PART + u * 16) * 4u;
        if (h == 1) {
            #pragma unroll
            for (int i = 0; i < 4; ++i) sts16(pA + i * 16u, acc[i][0], acc[i][1]);
        }
        __syncthreads();
        if (h == 0) {
            float4 w2v = *(const float4*)(sm + SM_W2 + 32 + e0);
            float4 w2f = *(const float4*)(sm + SM_W2 + e0);
            float part[4];
            #pragma unroll
            for (int i = 0; i < 4; ++i) {
                ull lo, hi; lds16(lo, hi, pA + i * 16u);
                add2(acc[i][0], acc[i][0], lo);
                add2(acc[i][1], acc[i][1], hi);
                float2 p0 = unpack2(acc[i][0]), p1 = unpack2(acc[i][1]);
                float4 fr = *(const float4*)(sm + SM_FI + (i0 + i) * 36 + e0);
                part[i] = p0.x * w2v.x + p0.y * w2v.y + p1.x * w2v.z + p1.y * w2v.w
                        + fr.x * w2f.x + fr.y * w2f.y + fr.z * w2f.z + fr.w * w2f.w;
            }
            #pragma unroll
            for (int msk = 1; msk <= 4; msk <<= 1) {
                #pragma unroll
                for (int i = 0; i < 4; ++i)
                    part[i] += __shfl_xor_sync(0xffffffffu, part[i], msk);
            }
            if (eg == 0) {
                float b2v = sm[SM_B2];
                float4 o;
                o.x = 1.0f / (1.0f + __expf(-(part[0] + b2v)));
                o.y = 1.0f / (1.0f + __expf(-(part[1] + b2v)));
                o.z = 1.0f / (1.0f + __expf(-(part[2] + b2v)));
                o.w = 1.0f / (1.0f + __expf(-(part[3] + b2v)));
                *(float4*)(out + (size_t)b * NAG + i0) = o;
            }
        }
    }
}

extern "C" void kernel_launch(void* const* d_in, const int* in_sizes, int n_in,
                              void* d_out, int out_size)
{
    const float* inp = (const float*)d_in[0];
    const float* W1  = (const float*)d_in[1];
    const float* b1  = (const float*)d_in[2];
    const float* C   = (const float*)d_in[3];
    const float* W2  = (const float*)d_in[4];
    const float* b2  = (const float*)d_in[5];
    float* out = (float*)d_out;

    const int smem_bytes = SM_TOTAL * (int)sizeof(float);
    cudaFuncSetAttribute(attn_fused_kernel,
                         cudaFuncAttributeMaxDynamicSharedMemorySize, smem_bytes);
    attn_fused_kernel<<<BATCH, 256, smem_bytes>>>(inp, W1, b1, C, W2, b2, out);
}